// round 15
// baseline (speedup 1.0000x reference)
#include <cuda_runtime.h>
#include <cuda_fp16.h>
#include <math.h>

// Problem constants
#define BZ 32
#define TT 256
#define EE 1024
#define HH 1024
#define KK 2048
#define C4 4096
#define NMT 256           // m-tiles (16 cols) per layer (old layout, x0 only)
#define NCHUNK 128        // k-chunks of 16
#define BROW 1032         // staged B row stride in halves (2064 B)
#define BMATB 66048       // bytes per staged 32x1024 fp16 matrix
#define PART_F (24 * 16 * 33)                  // 24 jobs x 16 rows x 33
#define SMEM_STEP (2 * BMATB + PART_F * 4)     // 182784 B
#define X0ROW 136         // x0 staged row stride in halves (272 B)
#define X0SM (2 * 64 * X0ROW * 2)    // 34816 B

// ---------------------------------------------------------------------------
// Device scratch (static; no allocations)
// ---------------------------------------------------------------------------
__device__ __half g_Wt[2][C4][KK];              // transposed weights, fp16
__device__ uint4  g_Wsw[2 * NMT * NCHUNK * 32]; // old-layout frags (x0_gemm)
__device__ uint4  g_WsA0[128 * 2 * 64 * 32];    // L0 step frags (gate-interleaved)
__device__ uint4  g_WsA1[128 * 2 * 128 * 32];   // L1 step frags (gate-interleaved)
__device__ __half g_x[TT * BZ][EE];             // x re-laid [t*32+b][e]
__device__ __half g_hf[2][2][BZ][HH];           // [parity][layer][b][j]
__device__ float  g_h[2][BZ][HH];
__device__ float  g_c[2][BZ][HH];
__device__ float  g_X0[(size_t)TT * C4 * BZ];   // x@W_ih0 + b0, [t][col][b]

// ---------------------------------------------------------------------------
// Helpers
// ---------------------------------------------------------------------------
__device__ __forceinline__ unsigned ldu(const __half* p) {
    return *reinterpret_cast<const unsigned*>(p);
}
__device__ __forceinline__ void mma16816(float d[4], const unsigned* a,
                                         unsigned b0, unsigned b1) {
    asm volatile(
        "mma.sync.aligned.m16n8k16.row.col.f32.f16.f16.f32 "
        "{%0,%1,%2,%3}, {%4,%5,%6,%7}, {%8,%9}, {%0,%1,%2,%3};\n"
        : "+f"(d[0]), "+f"(d[1]), "+f"(d[2]), "+f"(d[3])
        : "r"(a[0]), "r"(a[1]), "r"(a[2]), "r"(a[3]), "r"(b0), "r"(b1));
}
__device__ __forceinline__ void ldm4(unsigned r[4], unsigned addr) {
    asm volatile("ldmatrix.sync.aligned.m8n8.x4.shared.b16 {%0,%1,%2,%3}, [%4];"
                 : "=r"(r[0]), "=r"(r[1]), "=r"(r[2]), "=r"(r[3]) : "r"(addr));
}
__device__ __forceinline__ unsigned pack2(float lo, float hi) {
    __half2 h = __halves2half2(__float2half(lo), __float2half(hi));
    return *reinterpret_cast<unsigned*>(&h);
}
__device__ __forceinline__ float sigf(float x) { return 1.f / (1.f + __expf(-x)); }
__device__ __forceinline__ float tanhfast(float x) {
    float e2 = __expf(-2.f * fabsf(x));
    return copysignf((1.f - e2) / (1.f + e2), x);
}
__device__ __forceinline__ void gdc_launch() {
    asm volatile("griddepcontrol.launch_dependents;");
}
__device__ __forceinline__ void gdc_wait() {
    asm volatile("griddepcontrol.wait;" ::: "memory");
}

// ---------------------------------------------------------------------------
// Prep: transpose + convert; writes g_Wt AND old-layout g_Wsw frags (for x0).
// ---------------------------------------------------------------------------
__global__ void prep_weights(const float* __restrict__ W_ih0,
                             const float* __restrict__ W_hh0,
                             const float* __restrict__ W_ih1,
                             const float* __restrict__ W_hh1)
{
    __shared__ float tile[32][33];   // tile[k_local][c_local]
    int k0 = blockIdx.x * 32;
    int c0 = blockIdx.y * 32;
    int L  = blockIdx.z;
    int tx = threadIdx.x, ty = threadIdx.y;
#pragma unroll
    for (int i = 0; i < 4; i++) {
        int k = k0 + ty + i * 8;
        const float* S; int kr;
        if (L == 0) { if (k < HH) { S = W_hh0; kr = k; } else { S = W_ih0; kr = k - HH; } }
        else        { if (k < HH) { S = W_ih1; kr = k; } else { S = W_hh1; kr = k - HH; } }
        tile[ty + i * 8][tx] = S[(size_t)kr * C4 + c0 + tx];
    }
    __syncthreads();

    // g_Wt write (transposed fp16)
#pragma unroll
    for (int i = 0; i < 4; i++) {
        int c = c0 + ty + i * 8;
        g_Wt[L][c][k0 + tx] = __float2half(tile[tx][ty + i * 8]);
    }

    // old-layout fragment pack (x0_gemm consumes L0 chunks 64..127)
    const int tid = ty * 32 + tx;
    if (tid < 128) {
        const int fi   = tid >> 5;
        const int lane = tid & 31;
        const int mt_l = fi >> 1;
        const int ch_l = fi & 1;
        const int r  = lane >> 2;
        const int ka = (lane & 3) * 2;
        const int cl0 = mt_l * 16 + r;
        const int cl1 = cl0 + 8;
        const int kl  = ch_l * 16 + ka;
        uint4 f;
        f.x = pack2(tile[kl][cl0],     tile[kl + 1][cl0]);
        f.y = pack2(tile[kl][cl1],     tile[kl + 1][cl1]);
        f.z = pack2(tile[kl + 8][cl0], tile[kl + 9][cl0]);
        f.w = pack2(tile[kl + 8][cl1], tile[kl + 9][cl1]);
        const int mt = (c0 >> 4) + mt_l;
        const int ch = (k0 >> 4) + ch_l;
        g_Wsw[(((size_t)L * NMT + mt) * NCHUNK + ch) * 32 + lane] = f;
    }
}

// Gate-interleaved step fragments. m-tile rows 0-7 -> gate mt*2, rows 8-15 ->
// gate mt*2+1, unit = blk*8 + r.
__global__ void swz_A0()
{
    const int idx = blockIdx.x * blockDim.x + threadIdx.x;   // 524288
    const int lane = idx & 31;
    const int ch   = (idx >> 5) & 63;
    const int mt   = (idx >> 11) & 1;
    const int blk  = idx >> 12;
    const int r  = lane >> 2;
    const int ka = (lane & 3) * 2;
    const int col0 = (mt * 2) * HH + blk * 8 + r;
    const int col1 = (mt * 2 + 1) * HH + blk * 8 + r;
    const int k0 = ch * 16 + ka;
    uint4 f;
    f.x = ldu(&g_Wt[0][col0][k0]);
    f.y = ldu(&g_Wt[0][col1][k0]);
    f.z = ldu(&g_Wt[0][col0][k0 + 8]);
    f.w = ldu(&g_Wt[0][col1][k0 + 8]);
    g_WsA0[idx] = f;
}

__global__ void swz_A1()
{
    const int idx = blockIdx.x * blockDim.x + threadIdx.x;   // 1048576
    const int lane = idx & 31;
    const int ch   = (idx >> 5) & 127;
    const int mt   = (idx >> 12) & 1;
    const int blk  = idx >> 13;
    const int r  = lane >> 2;
    const int ka = (lane & 3) * 2;
    const int col0 = (mt * 2) * HH + blk * 8 + r;
    const int col1 = (mt * 2 + 1) * HH + blk * 8 + r;
    const int k0 = ch * 16 + ka;
    uint4 f;
    f.x = ldu(&g_Wt[1][col0][k0]);
    f.y = ldu(&g_Wt[1][col1][k0]);
    f.z = ldu(&g_Wt[1][col0][k0 + 8]);
    f.w = ldu(&g_Wt[1][col1][k0 + 8]);
    g_WsA1[idx] = f;
}

__global__ void prep_x(const float* __restrict__ x)
{
    const int N = BZ * TT * EE;
    for (int idx = blockIdx.x * blockDim.x + threadIdx.x; idx < N;
         idx += gridDim.x * blockDim.x) {
        int e  = idx & (EE - 1);
        int bt = idx >> 10;
        int t  = bt & (TT - 1);
        int b  = bt >> 8;
        g_x[t * BZ + b][e] = __float2half(x[idx]);
    }
}

__global__ void zero_states()
{
    int idx = blockIdx.x * blockDim.x + threadIdx.x;
    const int nhf = 2 * 2 * BZ * HH;
    if (idx < nhf) (&g_hf[0][0][0][0])[idx] = __float2half(0.f);
    const int nf = 2 * BZ * HH;
    if (idx < nf) {
        (&g_h[0][0][0])[idx] = 0.f;
        (&g_c[0][0][0])[idx] = 0.f;
    }
}

__global__ void copy_mask(const float* __restrict__ m, float* __restrict__ dst)
{
    int i = blockIdx.x * blockDim.x + threadIdx.x;
    if (i < BZ * TT) dst[i] = m[i];
}

// ---------------------------------------------------------------------------
// X0 precompute v4 (R14, unchanged).
// ---------------------------------------------------------------------------
__global__ void __launch_bounds__(256, 2) x0_gemm(const float* __restrict__ b0)
{
    extern __shared__ __align__(16) unsigned char sm[];
    const unsigned smbase = (unsigned)__cvta_generic_to_shared(sm);
    const int cg   = blockIdx.x;
    const int rg   = blockIdx.y;
    const int tid  = threadIdx.x;
    const int lane = tid & 31;
    const int w    = tid >> 5;
    const int mtA  = cg * 16 + w * 2;
    const int mtB  = mtA + 1;

    const uint4* __restrict__ A0 = g_Wsw + ((size_t)mtA * NCHUNK + 64) * 32 + lane;
    const uint4* __restrict__ A1 = g_Wsw + ((size_t)mtB * NCHUNK + 64) * 32 + lane;

    const int row0 = rg * 64;
    auto stage = [&](int s, int buf) {
#pragma unroll
        for (int q = 0; q < 4; q++) {
            int idx = tid + q * 256;
            int row = idx >> 4, kc = idx & 15;
            const __half* src = &g_x[row0 + row][s * 128 + kc * 8];
            unsigned dst = smbase + buf * (64 * X0ROW * 2) + row * (X0ROW * 2) + kc * 16;
            asm volatile("cp.async.ca.shared.global [%0], [%1], 16;\n"
                         :: "r"(dst), "l"(src));
        }
        asm volatile("cp.async.commit_group;\n");
    };

    const int ltile = lane >> 3, lrow = lane & 7;
    const int nbb = (ltile >> 1) * 8 + lrow;
    const int kb  = (ltile & 1) * 8;

    float acc0[4][8], acc1[4][8];
#pragma unroll
    for (int ng = 0; ng < 4; ng++)
#pragma unroll
        for (int q = 0; q < 8; q++) { acc0[ng][q] = 0.f; acc1[ng][q] = 0.f; }

    stage(0, 0);

    for (int s = 0; s < 8; s++) {
        const int buf = s & 1;
        if (s < 7) {
            stage(s + 1, buf ^ 1);
            asm volatile("cp.async.wait_group 1;\n");
        } else {
            asm volatile("cp.async.wait_group 0;\n");
        }
        __syncthreads();

        const unsigned bbase = smbase + buf * (64 * X0ROW * 2);
        uint4 Ac0 = A0[(s * 8) * 32];
        uint4 Ac1 = A1[(s * 8) * 32];
#pragma unroll
        for (int c = 0; c < 8; c++) {
            uint4 An0, An1;
            if (c < 7) { An0 = A0[(s * 8 + c + 1) * 32]; An1 = A1[(s * 8 + c + 1) * 32]; }
            const unsigned kco = c * 32;
            const unsigned* ap0 = reinterpret_cast<const unsigned*>(&Ac0);
            const unsigned* ap1 = reinterpret_cast<const unsigned*>(&Ac1);
#pragma unroll
            for (int ng = 0; ng < 4; ng++) {
                unsigned bb[4];
                ldm4(bb, bbase + ((unsigned)((ng * 16 + nbb) * X0ROW + kb) << 1) + kco);
                mma16816(&acc0[ng][0], ap0, bb[0], bb[1]);
                mma16816(&acc0[ng][4], ap0, bb[2], bb[3]);
                mma16816(&acc1[ng][0], ap1, bb[0], bb[1]);
                mma16816(&acc1[ng][4], ap1, bb[2], bb[3]);
            }
            Ac0 = An0; Ac1 = An1;
        }
        __syncthreads();
    }

    const int nb = (lane & 3) * 2;
#pragma unroll
    for (int mi = 0; mi < 2; mi++) {
        const int mt = mi ? mtB : mtA;
        const int colr = mt * 16 + (lane >> 2);
        const float bia0 = b0[colr];
        const float bia8 = b0[colr + 8];
#pragma unroll
        for (int ng = 0; ng < 4; ng++) {
            const int r = row0 + ng * 16;
            const int t = r >> 5;
            const size_t base = (size_t)t * C4 * BZ;
            const float* accp = mi ? &acc1[ng][0] : &acc0[ng][0];
#pragma unroll
            for (int half = 0; half < 2; half++) {
                const int bb = ((ng * 16 + half * 8 + nb) & 31);
                const float* a4 = accp + half * 4;
                g_X0[base + (size_t)colr * 32 + bb]           = a4[0] + bia0;
                g_X0[base + (size_t)colr * 32 + bb + 1]       = a4[1] + bia0;
                g_X0[base + (size_t)(colr + 8) * 32 + bb]     = a4[2] + bia8;
                g_X0[base + (size_t)(colr + 8) * 32 + bb + 1] = a4[3] + bia8;
            }
        }
    }
}

// ---------------------------------------------------------------------------
// Balanced timestep. 128 blocks x 256 threads; every block: 8 L0 units +
// 8 L1 units (1536 HMMA each). Warp w runs 3 jobs of 16 chunks:
//   w<4 : L1(mt0,oct w)[h0], L1(mt1,oct w)[h0], L0(mt0,qt w)[h0]
//   w>=4: L0(mt1,qt w-4)[h0], L1(mt0,oct w)[h1], L1(mt1,oct w)[h1]
// h0 staged by all threads (group A); h1 staged by warps 4-7 only (group B,
// self-contained wait + named barrier). PDL + prologue prefetch retained.
// ---------------------------------------------------------------------------
__global__ void __launch_bounds__(256) lstm_step(
    int t,
    const float* __restrict__ mask,
    const float* __restrict__ bias1,
    float* __restrict__ out)
{
    gdc_launch();

    extern __shared__ __align__(16) unsigned char sm[];
    const unsigned smbase = (unsigned)__cvta_generic_to_shared(sm);
    float* part = reinterpret_cast<float*>(sm + 2 * BMATB);

    const int blk  = blockIdx.x;
    const int tid  = threadIdx.x;
    const int lane = tid & 31;
    const int w    = tid >> 5;
    const int p    = t & 1;

    // ---- job table ----
    int jis1[3], jmt[3], joff[3];
    if (w < 4) {
        jis1[0] = 1; jmt[0] = 0; joff[0] = w;
        jis1[1] = 1; jmt[1] = 1; joff[1] = w;
        jis1[2] = 0; jmt[2] = 0; joff[2] = w;
    } else {
        jis1[0] = 0; jmt[0] = 1; joff[0] = w - 4;
        jis1[1] = 1; jmt[1] = 0; joff[1] = w;
        jis1[2] = 1; jmt[2] = 1; joff[2] = w;
    }
    const uint4* Aj[3];
    int pidx[3], jmat[3], jks[3];
#pragma unroll
    for (int jj = 0; jj < 3; jj++) {
        if (jis1[jj]) {
            Aj[jj] = g_WsA1 + ((size_t)(blk * 2 + jmt[jj]) * 128 + joff[jj] * 16) * 32 + lane;
            pidx[jj] = jmt[jj] * 8 + joff[jj];
            jmat[jj] = (joff[jj] >= 4);
            jks[jj]  = (joff[jj] & 3) * 16;
        } else {
            Aj[jj] = g_WsA0 + ((size_t)(blk * 2 + jmt[jj]) * 64 + joff[jj] * 16) * 32 + lane;
            pidx[jj] = 16 + jmt[jj] * 4 + joff[jj];
            jmat[jj] = 0;
            jks[jj]  = joff[jj] * 16;
        }
    }

    // ---- PRE-SYNC: A preload (job0 batch0) + read-only operand prefetch ----
    uint4 Ac[4], An[4];
#pragma unroll
    for (int cc = 0; cc < 4; cc++) Ac[cc] = Aj[0][cc * 32];

    const int pu = tid & 7;
    const int pb = tid >> 3;
    const int pj = blk * 8 + pu;
    const float mpre = mask[pb * TT + t];
    float x0p[4], b1p[4];
#pragma unroll
    for (int q = 0; q < 4; q++) {
        x0p[q] = g_X0[(size_t)t * C4 * BZ + (size_t)(q * HH + pj) * 32 + pb];
        b1p[q] = bias1[q * HH + pj];
    }

    // ldmatrix lane geometry
    const int ltile = lane >> 3, lrow = lane & 7;
    const int nbb = (ltile >> 1) * 8 + lrow;
    const int kb  = (ltile & 1) * 8;
    unsigned ldmb[3][2];
#pragma unroll
    for (int jj = 0; jj < 3; jj++)
#pragma unroll
        for (int ng = 0; ng < 2; ng++)
            ldmb[jj][ng] = smbase + jmat[jj] * BMATB +
                (((unsigned)(ng * 16 + nbb) * BROW + jks[jj] * 16 + kb) << 1);

    // ---- wait for previous step ----
    gdc_wait();

    // ---- staging: h0 (all threads, group A) then h1 (warps 4-7, group B) ----
    const __half* __restrict__ h0 = &g_hf[p][0][0][0];
    const __half* __restrict__ h1 = &g_hf[p][1][0][0];
#pragma unroll
    for (int q = 0; q < 16; q++) {
        int idx = tid + q * 256;
        int row = idx >> 7, kc = idx & 127;
        const __half* src = h0 + row * HH + kc * 8;
        unsigned dst = smbase + row * 2064 + kc * 16;
        asm volatile("cp.async.ca.shared.global [%0], [%1], 16;\n"
                     :: "r"(dst), "l"(src));
    }
    asm volatile("cp.async.commit_group;\n");
    if (w >= 4) {
        const int tg = tid - 128;
#pragma unroll
        for (int q = 0; q < 32; q++) {
            int idx = tg + q * 128;
            int row = idx >> 7, kc = idx & 127;
            const __half* src = h1 + row * HH + kc * 8;
            unsigned dst = smbase + BMATB + row * 2064 + kc * 16;
            asm volatile("cp.async.ca.shared.global [%0], [%1], 16;\n"
                         :: "r"(dst), "l"(src));
        }
    }
    asm volatile("cp.async.commit_group;\n");

    // ---- c/h prefetch (written by step t-1) ----
    const float c0p = g_c[0][pb][pj];
    const float h0p = g_h[0][pb][pj];
    const float c1p = g_c[1][pb][pj];
    const float h1p = g_h[1][pb][pj];

    // h0 ready for everyone
    asm volatile("cp.async.wait_group 1;\n");
    __syncthreads();

    // ---- 3 jobs ----
#pragma unroll
    for (int jj = 0; jj < 3; jj++) {
        if (w >= 4 && jj == 1) {
            asm volatile("cp.async.wait_group 0;\n");
            asm volatile("bar.sync 1, 128;\n" ::: "memory");
        }
        float acc[4][4];
#pragma unroll
        for (int j = 0; j < 4; j++)
#pragma unroll
            for (int q = 0; q < 4; q++) acc[j][q] = 0.f;

#pragma unroll
        for (int ct = 0; ct < 4; ct++) {
            if (ct < 3) {
#pragma unroll
                for (int cc = 0; cc < 4; cc++) An[cc] = Aj[jj][((ct + 1) * 4 + cc) * 32];
            } else if (jj < 2) {
#pragma unroll
                for (int cc = 0; cc < 4; cc++) An[cc] = Aj[jj + 1][cc * 32];
            }
#pragma unroll
            for (int cc = 0; cc < 4; cc++) {
                const int c = ct * 4 + cc;
                unsigned b01[4], b23[4];
                ldm4(b01, ldmb[jj][0] + c * 32);
                ldm4(b23, ldmb[jj][1] + c * 32);
                const unsigned* ap = reinterpret_cast<const unsigned*>(&Ac[cc]);
                mma16816(acc[0], ap, b01[0], b01[1]);
                mma16816(acc[1], ap, b01[2], b01[3]);
                mma16816(acc[2], ap, b23[0], b23[1]);
                mma16816(acc[3], ap, b23[2], b23[3]);
            }
#pragma unroll
            for (int cc = 0; cc < 4; cc++) Ac[cc] = An[cc];
        }

        // write partial [pidx][16][33]
        const int r  = lane >> 2;
        const int q2 = (lane & 3) * 2;
        float* pp = part + pidx[jj] * (16 * 33);
#pragma unroll
        for (int jn = 0; jn < 4; jn++) {
            const int n = jn * 8 + q2;
            pp[r * 33 + n]           = acc[jn][0];
            pp[r * 33 + n + 1]       = acc[jn][1];
            pp[(r + 8) * 33 + n]     = acc[jn][2];
            pp[(r + 8) * 33 + n + 1] = acc[jn][3];
        }
    }
    __syncthreads();

    // ---- fused pointwise: thread -> (unit pu, batch pb) for BOTH layers ----
    // Layer 0: 4 quarter-partials per gate + X0
    {
        float g4[4];
#pragma unroll
        for (int q = 0; q < 4; q++) {
            const int rr = (q & 1) * 8 + pu;
            const float* pq = part + (16 + (q >> 1) * 4) * (16 * 33) + rr * 33 + pb;
            g4[q] = pq[0] + pq[16 * 33] + pq[2 * 16 * 33] + pq[3 * 16 * 33] + x0p[q];
        }
        float cn = sigf(g4[0]) * c0p + sigf(g4[1]) * tanhfast(g4[3]);
        cn = cn * mpre + c0p * (1.f - mpre);
        float hn = sigf(g4[2]) * tanhfast(cn);
        hn = hn * mpre + h0p * (1.f - mpre);
        g_c[0][pb][pj] = cn;
        g_h[0][pb][pj] = hn;
        g_hf[p ^ 1][0][pb][pj] = __float2half(hn);
    }
    // Layer 1: 8 octant-partials per gate + bias1
    {
        float g4[4];
#pragma unroll
        for (int q = 0; q < 4; q++) {
            const int rr = (q & 1) * 8 + pu;
            const float* pq = part + ((q >> 1) * 8) * (16 * 33) + rr * 33 + pb;
            float v = 0.f;
#pragma unroll
            for (int o = 0; o < 8; o++) v += pq[o * (16 * 33)];
            g4[q] = v + b1p[q];
        }
        float cn = sigf(g4[0]) * c1p + sigf(g4[1]) * tanhfast(g4[3]);
        cn = cn * mpre + c1p * (1.f - mpre);
        float hn = sigf(g4[2]) * tanhfast(cn);
        hn = hn * mpre + h1p * (1.f - mpre);
        g_c[1][pb][pj] = cn;
        g_h[1][pb][pj] = hn;
        g_hf[p ^ 1][1][pb][pj] = __float2half(hn);
        out[((size_t)pb * TT + t) * HH + pj] = hn;
    }
}

// ---------------------------------------------------------------------------
extern "C" void kernel_launch(void* const* d_in, const int* in_sizes, int n_in,
                              void* d_out, int out_size)
{
    const float* x     = (const float*)d_in[0];
    const float* mask  = (const float*)d_in[1];
    const float* W_ih0 = (const float*)d_in[2];
    const float* W_hh0 = (const float*)d_in[3];
    const float* bs0   = (const float*)d_in[4];
    const float* W_ih1 = (const float*)d_in[5];
    const float* W_hh1 = (const float*)d_in[6];
    const float* bs1   = (const float*)d_in[7];
    float* out = (float*)d_out;

    static bool attr_done = false;
    if (!attr_done) {
        cudaFuncSetAttribute(x0_gemm, cudaFuncAttributeMaxDynamicSharedMemorySize, X0SM);
        cudaFuncSetAttribute(lstm_step, cudaFuncAttributeMaxDynamicSharedMemorySize, SMEM_STEP);
        attr_done = true;
    }

    prep_weights<<<dim3(KK / 32, C4 / 32, 2), dim3(32, 8)>>>(W_ih0, W_hh0, W_ih1, W_hh1);
    swz_A0<<<524288 / 256, 256>>>();
    swz_A1<<<1048576 / 256, 256>>>();
    prep_x<<<1024, 256>>>(x);
    zero_states<<<512, 256>>>();
    x0_gemm<<<dim3(16, 128), 256, X0SM>>>(bs0);

    // PDL chain over the 256 dependent step kernels
    cudaLaunchAttribute attrs[1];
    attrs[0].id = cudaLaunchAttributeProgrammaticStreamSerialization;
    attrs[0].val.programmaticStreamSerializationAllowed = 1;

    cudaLaunchConfig_t cfg = {};
    cfg.gridDim  = dim3(128, 1, 1);
    cfg.blockDim = dim3(256, 1, 1);
    cfg.dynamicSmemBytes = SMEM_STEP;
    cfg.stream = 0;
    cfg.attrs = attrs;
    cfg.numAttrs = 1;

    for (int t = 0; t < TT; t++) {
        cudaLaunchKernelEx(&cfg, lstm_step, t, mask, bs1, out);
    }

    if (out_size >= BZ * TT * HH + BZ * TT) {
        copy_mask<<<(BZ * TT + 255) / 256, 256>>>(mask, out + (size_t)BZ * TT * HH);
    }
}

// round 16
// speedup vs baseline: 1.1248x; 1.1248x over previous
#include <cuda_runtime.h>
#include <cuda_fp16.h>
#include <math.h>

// Problem constants
#define BZ 32
#define TT 256
#define EE 1024
#define KK 2048
#define HH 1024
#define C4 4096
#define NMT 256           // m-tiles (16 cols) per layer
#define NCHUNK 128        // k-chunks of 16
#define BROW 1032         // staged B row stride in halves (2064 B)
#define BMATB 66048       // bytes per staged 32x1024 fp16 matrix
#define PRES_OFF (2 * BMATB)              // dedicated preS region
#define PRES_BYTES (2 * 64 * 33 * 4)      // [2][64][33] floats = 16896 B
#define SMEM_STEP (PRES_OFF + PRES_BYTES) // 148992 B
#define X0ROW 136         // x0 staged row stride in halves (272 B)
#define X0BUF (64 * X0ROW * 2)       // one 64x128 fp16 slice buffer (17408 B)
#define X0SM (3 * X0BUF)             // triple-buffered (52224 B)

// ---------------------------------------------------------------------------
// Device scratch (static; no allocations)
// ---------------------------------------------------------------------------
__device__ uint4  g_Wsw[2 * NMT * NCHUNK * 32]; // mma A fragments (packed direct)
__device__ __half g_x[TT * BZ][EE];             // x re-laid [t*32+b][e]
__device__ __half g_hf[2][2][BZ][HH];           // [parity][layer][b][j]
__device__ float  g_h[2][BZ][HH];
__device__ float  g_c[2][BZ][HH];
__device__ float  g_X0[(size_t)TT * C4 * BZ];   // x@W_ih0 + b0, [t][col][b]

// ---------------------------------------------------------------------------
// Helpers
// ---------------------------------------------------------------------------
__device__ __forceinline__ void mma16816(float d[4], const unsigned* a,
                                         unsigned b0, unsigned b1) {
    asm volatile(
        "mma.sync.aligned.m16n8k16.row.col.f32.f16.f16.f32 "
        "{%0,%1,%2,%3}, {%4,%5,%6,%7}, {%8,%9}, {%0,%1,%2,%3};\n"
        : "+f"(d[0]), "+f"(d[1]), "+f"(d[2]), "+f"(d[3])
        : "r"(a[0]), "r"(a[1]), "r"(a[2]), "r"(a[3]), "r"(b0), "r"(b1));
}
__device__ __forceinline__ void ldm4(unsigned r[4], unsigned addr) {
    asm volatile("ldmatrix.sync.aligned.m8n8.x4.shared.b16 {%0,%1,%2,%3}, [%4];"
                 : "=r"(r[0]), "=r"(r[1]), "=r"(r[2]), "=r"(r[3]) : "r"(addr));
}
__device__ __forceinline__ unsigned pack2(float lo, float hi) {
    __half2 h = __halves2half2(__float2half(lo), __float2half(hi));
    return *reinterpret_cast<unsigned*>(&h);
}
__device__ __forceinline__ float sigf(float x) { return 1.f / (1.f + __expf(-x)); }
__device__ __forceinline__ float tanhfast(float x) {
    float e2 = __expf(-2.f * fabsf(x));
    return copysignf((1.f - e2) / (1.f + e2), x);
}
// PDL controls
__device__ __forceinline__ void gdc_launch() {
    asm volatile("griddepcontrol.launch_dependents;");
}
__device__ __forceinline__ void gdc_wait() {
    asm volatile("griddepcontrol.wait;" ::: "memory");
}

// ---------------------------------------------------------------------------
// Prep: transpose + convert + pack mma fragments DIRECTLY (R12 version).
// ---------------------------------------------------------------------------
__global__ void prep_weights(const float* __restrict__ W_ih0,
                             const float* __restrict__ W_hh0,
                             const float* __restrict__ W_ih1,
                             const float* __restrict__ W_hh1)
{
    __shared__ float tile[32][33];   // tile[k_local][c_local]
    int k0 = blockIdx.x * 32;
    int c0 = blockIdx.y * 32;
    int L  = blockIdx.z;
    int tx = threadIdx.x, ty = threadIdx.y;
#pragma unroll
    for (int i = 0; i < 4; i++) {
        int k = k0 + ty + i * 8;
        const float* S; int kr;
        if (L == 0) { if (k < HH) { S = W_hh0; kr = k; } else { S = W_ih0; kr = k - HH; } }
        else        { if (k < HH) { S = W_ih1; kr = k; } else { S = W_hh1; kr = k - HH; } }
        tile[ty + i * 8][tx] = S[(size_t)kr * C4 + c0 + tx];
    }
    __syncthreads();

    const int tid = ty * 32 + tx;
    if (tid < 128) {
        const int fi   = tid >> 5;
        const int lane = tid & 31;
        const int mt_l = fi >> 1;
        const int ch_l = fi & 1;
        const int r  = lane >> 2;
        const int ka = (lane & 3) * 2;
        const int cl0 = mt_l * 16 + r;
        const int cl1 = cl0 + 8;
        const int kl  = ch_l * 16 + ka;
        uint4 f;
        f.x = pack2(tile[kl][cl0],     tile[kl + 1][cl0]);
        f.y = pack2(tile[kl][cl1],     tile[kl + 1][cl1]);
        f.z = pack2(tile[kl + 8][cl0], tile[kl + 9][cl0]);
        f.w = pack2(tile[kl + 8][cl1], tile[kl + 9][cl1]);
        const int mt = (c0 >> 4) + mt_l;
        const int ch = (k0 >> 4) + ch_l;
        g_Wsw[(((size_t)L * NMT + mt) * NCHUNK + ch) * 32 + lane] = f;
    }
}

// Vectorized x relayout: 8 elems/thread (2x float4 load, 1x uint4 store).
__global__ void prep_x(const float* __restrict__ x)
{
    const int N8 = BZ * TT * EE / 8;
    for (int idx = blockIdx.x * blockDim.x + threadIdx.x; idx < N8;
         idx += gridDim.x * blockDim.x) {
        const int e8 = idx & 127;            // e / 8
        const int bt = idx >> 7;             // b*TT + t
        const int t  = bt & (TT - 1);
        const int b  = bt >> 8;
        const float4* src = reinterpret_cast<const float4*>(x + (size_t)bt * EE + e8 * 8);
        float4 a = src[0];
        float4 c = src[1];
        uint4 o;
        o.x = pack2(a.x, a.y);
        o.y = pack2(a.z, a.w);
        o.z = pack2(c.x, c.y);
        o.w = pack2(c.z, c.w);
        *reinterpret_cast<uint4*>(&g_x[t * BZ + b][e8 * 8]) = o;
    }
}

__global__ void zero_states()
{
    int idx = blockIdx.x * blockDim.x + threadIdx.x;
    const int nhf = 2 * 2 * BZ * HH;
    if (idx < nhf) (&g_hf[0][0][0][0])[idx] = __float2half(0.f);
    const int nf = 2 * BZ * HH;
    if (idx < nf) {
        (&g_h[0][0][0])[idx] = 0.f;
        (&g_c[0][0][0])[idx] = 0.f;
    }
}

__global__ void copy_mask(const float* __restrict__ m, float* __restrict__ dst)
{
    int i = blockIdx.x * blockDim.x + threadIdx.x;
    if (i < BZ * TT) dst[i] = m[i];
}

// ---------------------------------------------------------------------------
// X0 precompute v5: R14's v4 (2 m-tiles/warp, 64-row tile, occ 2) with a
// TRIPLE-buffered k-slice pipeline (stage distance 2) so slice-boundary
// waits rarely bind. Slice/chunk order unchanged -> bit-identical results.
// ---------------------------------------------------------------------------
__global__ void __launch_bounds__(256, 2) x0_gemm(const float* __restrict__ b0)
{
    extern __shared__ __align__(16) unsigned char sm[];
    const unsigned smbase = (unsigned)__cvta_generic_to_shared(sm);
    const int cg   = blockIdx.x;          // 256-col group (0..15)
    const int rg   = blockIdx.y;          // 64-row group (0..127)
    const int tid  = threadIdx.x;
    const int lane = tid & 31;
    const int w    = tid >> 5;
    const int mtA  = cg * 16 + w * 2;
    const int mtB  = mtA + 1;

    const uint4* __restrict__ A0 = g_Wsw + ((size_t)mtA * NCHUNK + 64) * 32 + lane;
    const uint4* __restrict__ A1 = g_Wsw + ((size_t)mtB * NCHUNK + 64) * 32 + lane;

    const int row0 = rg * 64;
    auto stage = [&](int s) {
        const int buf = s % 3;
#pragma unroll
        for (int q = 0; q < 4; q++) {
            int idx = tid + q * 256;
            int row = idx >> 4, kc = idx & 15;
            const __half* src = &g_x[row0 + row][s * 128 + kc * 8];
            unsigned dst = smbase + buf * X0BUF + row * (X0ROW * 2) + kc * 16;
            asm volatile("cp.async.ca.shared.global [%0], [%1], 16;\n"
                         :: "r"(dst), "l"(src));
        }
        asm volatile("cp.async.commit_group;\n");
    };

    const int ltile = lane >> 3, lrow = lane & 7;
    const int nbb = (ltile >> 1) * 8 + lrow;
    const int kb  = (ltile & 1) * 8;

    float acc0[4][8], acc1[4][8];
#pragma unroll
    for (int ng = 0; ng < 4; ng++)
#pragma unroll
        for (int q = 0; q < 8; q++) { acc0[ng][q] = 0.f; acc1[ng][q] = 0.f; }

    stage(0);
    stage(1);

    for (int s = 0; s < 8; s++) {
        if (s < 7) asm volatile("cp.async.wait_group 1;\n");
        else       asm volatile("cp.async.wait_group 0;\n");
        __syncthreads();                   // all warps done with buf[(s-1)%3]
        if (s < 6) stage(s + 2);           // refill the freed buffer

        const unsigned bbase = smbase + (s % 3) * X0BUF;
        uint4 Ac0 = A0[(s * 8) * 32];
        uint4 Ac1 = A1[(s * 8) * 32];
#pragma unroll
        for (int c = 0; c < 8; c++) {
            uint4 An0, An1;
            if (c < 7) { An0 = A0[(s * 8 + c + 1) * 32]; An1 = A1[(s * 8 + c + 1) * 32]; }
            const unsigned kco = c * 32;
            const unsigned* ap0 = reinterpret_cast<const unsigned*>(&Ac0);
            const unsigned* ap1 = reinterpret_cast<const unsigned*>(&Ac1);
#pragma unroll
            for (int ng = 0; ng < 4; ng++) {
                unsigned bb[4];
                ldm4(bb, bbase + ((unsigned)((ng * 16 + nbb) * X0ROW + kb) << 1) + kco);
                mma16816(&acc0[ng][0], ap0, bb[0], bb[1]);
                mma16816(&acc0[ng][4], ap0, bb[2], bb[3]);
                mma16816(&acc1[ng][0], ap1, bb[0], bb[1]);
                mma16816(&acc1[ng][4], ap1, bb[2], bb[3]);
            }
            Ac0 = An0; Ac1 = An1;
        }
    }

    // Epilogue for both m-tiles
    const int nb = (lane & 3) * 2;
#pragma unroll
    for (int mi = 0; mi < 2; mi++) {
        const int mt = mi ? mtB : mtA;
        const int colr = mt * 16 + (lane >> 2);
        const float bia0 = b0[colr];
        const float bia8 = b0[colr + 8];
#pragma unroll
        for (int ng = 0; ng < 4; ng++) {
            const int r = row0 + ng * 16;
            const int t = r >> 5;
            const size_t base = (size_t)t * C4 * BZ;
            const float* accp = mi ? &acc1[ng][0] : &acc0[ng][0];
#pragma unroll
            for (int half = 0; half < 2; half++) {
                const int bb = ((ng * 16 + half * 8 + nb) & 31);
                const float* a4 = accp + half * 4;
                g_X0[base + (size_t)colr * 32 + bb]           = a4[0] + bia0;
                g_X0[base + (size_t)colr * 32 + bb + 1]       = a4[1] + bia0;
                g_X0[base + (size_t)(colr + 8) * 32 + bb]     = a4[2] + bia8;
                g_X0[base + (size_t)(colr + 8) * 32 + bb + 1] = a4[3] + bia8;
            }
        }
    }
}

// ---------------------------------------------------------------------------
// One timestep with PDL + k-sliced pipelined staging (L1) + dedicated preS.
// 128 blocks x 256 threads. (R14/R12 step kernel, unchanged.)
// ---------------------------------------------------------------------------
__global__ void __launch_bounds__(256) lstm_step(
    int t,
    const float* __restrict__ mask,
    const float* __restrict__ bias1,
    float* __restrict__ out)
{
    gdc_launch();   // let next step's blocks start their prologue ASAP

    extern __shared__ __align__(16) unsigned char sm[];
    const unsigned smbase = (unsigned)__cvta_generic_to_shared(sm);
    float* preS = reinterpret_cast<float*>(sm + PRES_OFF);   // dedicated [2][64][33]

    const int bx   = blockIdx.x;
    const int L    = bx >> 6;
    const int g    = bx & 63;
    const int tid  = threadIdx.x;
    const int lane = tid & 31;
    const int warp = tid >> 5;
    const int w    = warp & 3;
    const int hf   = warp >> 2;
    const int p    = t & 1;

    // ---- PRE-SYNC: A pointers + first-chunk preload (read-only) ----
    const int mt      = w * 64 + g;
    const int cbase   = L ? hf * 64 : hf * 32;
    const uint4* __restrict__ A =
        g_Wsw + (((size_t)L * NMT + mt) * NCHUNK + cbase) * 32 + lane;

    uint4 Ac[4], An[4];
#pragma unroll
    for (int cc = 0; cc < 4; cc++) Ac[cc] = A[cc * 32];

    // ---- PRE-SYNC: mask / X0 / bias prefetch (read-only) ----
    float mpre[2], addp[2][4];
#pragma unroll
    for (int it = 0; it < 2; it++) {
        const int e  = tid + it * 256;
        const int b  = e >> 4;
        const int ul = e & 15;
        const int j  = g * 16 + ul;
        mpre[it] = mask[b * TT + t];
        if (L == 0) {
            const size_t xb = (size_t)t * C4 * BZ + b;
#pragma unroll
            for (int q = 0; q < 4; q++)
                addp[it][q] = g_X0[xb + (size_t)(q * HH + j) * 32];
        } else {
#pragma unroll
            for (int q = 0; q < 4; q++)
                addp[it][q] = bias1[q * HH + j];
        }
    }

    // ldmatrix lane geometry (pure ALU)
    const int ltile = lane >> 3, lrow = lane & 7;
    const int nbb = (ltile >> 1) * 8 + lrow;
    const int kb  = (ltile & 1) * 8;
    const unsigned matoff = L ? hf * BMATB : hf * 1024;
    unsigned ldmb[2];
#pragma unroll
    for (int ng = 0; ng < 2; ng++)
        ldmb[ng] = smbase + matoff + (((ng * 16 + nbb) * BROW + kb) << 1);

    // ---- wait for previous step's writes to be visible ----
    gdc_wait();

    // ---- issue B staging ----
    const __half* __restrict__ h0 = &g_hf[p][0][0][0];
    const __half* __restrict__ h1 = &g_hf[p][1][0][0];
    if (L == 0) {
#pragma unroll
        for (int q = 0; q < 16; q++) {
            int idx = tid + q * 256;
            int row = idx >> 7, kc = idx & 127;
            const __half* src = h0 + row * HH + kc * 8;
            unsigned dst = smbase + row * 2064 + kc * 16;
            asm volatile("cp.async.ca.shared.global [%0], [%1], 16;\n"
                         :: "r"(dst), "l"(src));
        }
        asm volatile("cp.async.commit_group;\n");
    } else {
        // warp-group hf stages matrix hf in 4 k-slices (k-major order)
        const __half* __restrict__ srcm = hf ? h1 : h0;
        const int tg = tid & 127;
#pragma unroll
        for (int s = 0; s < 4; s++) {
#pragma unroll
            for (int q = 0; q < 8; q++) {
                int o   = tg + q * 128;          // [0,1024)
                int row = o >> 5;
                int kc  = s * 32 + (o & 31);
                const __half* src = srcm + row * HH + kc * 8;
                unsigned dst = smbase + hf * BMATB + row * 2064 + kc * 16;
                asm volatile("cp.async.ca.shared.global [%0], [%1], 16;\n"
                             :: "r"(dst), "l"(src));
            }
            asm volatile("cp.async.commit_group;\n");
        }
    }

    // ---- c/h prefetch (written by step t-1 -> post-wait) ----
    float cpre[2], hpre[2];
#pragma unroll
    for (int it = 0; it < 2; it++) {
        const int e  = tid + it * 256;
        const int b  = e >> 4;
        const int ul = e & 15;
        const int j  = g * 16 + ul;
        cpre[it] = g_c[L][b][j];
        hpre[it] = g_h[L][b][j];
    }

    // ---- mma ----
    float acc[4][4];
#pragma unroll
    for (int j = 0; j < 4; j++)
#pragma unroll
        for (int q = 0; q < 4; q++) acc[j][q] = 0.f;

    if (L == 0) {
        asm volatile("cp.async.wait_group 0;\n");
        __syncthreads();
        const int niter = 8;
        for (int ct = 0; ct < niter; ct++) {
            if (ct + 1 < niter) {
#pragma unroll
                for (int cc = 0; cc < 4; cc++) An[cc] = A[((ct + 1) * 4 + cc) * 32];
            }
#pragma unroll
            for (int cc = 0; cc < 4; cc++) {
                const int c = ct * 4 + cc;
                unsigned b01[4], b23[4];
                ldm4(b01, ldmb[0] + c * 32);
                ldm4(b23, ldmb[1] + c * 32);
                const unsigned* ap = reinterpret_cast<const unsigned*>(&Ac[cc]);
                mma16816(acc[0], ap, b01[0], b01[1]);
                mma16816(acc[1], ap, b01[2], b01[3]);
                mma16816(acc[2], ap, b23[0], b23[1]);
                mma16816(acc[3], ap, b23[2], b23[3]);
            }
#pragma unroll
            for (int cc = 0; cc < 4; cc++) Ac[cc] = An[cc];
        }
    } else {
        // 4 slices x 4 chunk-batches; wait per slice, overlap rest of staging
#pragma unroll
        for (int s = 0; s < 4; s++) {
            if (s == 0)      asm volatile("cp.async.wait_group 3;\n");
            else if (s == 1) asm volatile("cp.async.wait_group 2;\n");
            else if (s == 2) asm volatile("cp.async.wait_group 1;\n");
            else             asm volatile("cp.async.wait_group 0;\n");
            if (hf == 0) asm volatile("bar.sync 1, 128;\n" ::: "memory");
            else         asm volatile("bar.sync 2, 128;\n" ::: "memory");
#pragma unroll
            for (int cq = 0; cq < 4; cq++) {
                const int ct = s * 4 + cq;
                if (ct + 1 < 16) {
#pragma unroll
                    for (int cc = 0; cc < 4; cc++) An[cc] = A[((ct + 1) * 4 + cc) * 32];
                }
#pragma unroll
                for (int cc = 0; cc < 4; cc++) {
                    const int c = ct * 4 + cc;
                    unsigned b01[4], b23[4];
                    ldm4(b01, ldmb[0] + c * 32);
                    ldm4(b23, ldmb[1] + c * 32);
                    const unsigned* ap = reinterpret_cast<const unsigned*>(&Ac[cc]);
                    mma16816(acc[0], ap, b01[0], b01[1]);
                    mma16816(acc[1], ap, b01[2], b01[3]);
                    mma16816(acc[2], ap, b23[0], b23[1]);
                    mma16816(acc[3], ap, b23[2], b23[3]);
                }
#pragma unroll
                for (int cc = 0; cc < 4; cc++) Ac[cc] = An[cc];
            }
        }
    }

    // ---- reduce partials via dedicated preS (no alias -> no pre-barrier) ----
    {
        const int r = lane >> 2;
        const int q = (lane & 3) * 2;
        float* pS = preS + hf * (64 * 33);
#pragma unroll
        for (int j = 0; j < 4; j++) {
            const int n = j * 8 + q;
            pS[(w * 16 + r) * 33 + n]         = acc[j][0];
            pS[(w * 16 + r) * 33 + n + 1]     = acc[j][1];
            pS[(w * 16 + r + 8) * 33 + n]     = acc[j][2];
            pS[(w * 16 + r + 8) * 33 + n + 1] = acc[j][3];
        }
    }
    __syncthreads();

    // ---- fused pointwise LSTM update ----
#pragma unroll
    for (int it = 0; it < 2; it++) {
        const int e  = tid + it * 256;
        const int b  = e >> 4;
        const int ul = e & 15;
        const int j  = g * 16 + ul;
        float f  = preS[ul * 33 + b]        + preS[64 * 33 + ul * 33 + b]        + addp[it][0];
        float i  = preS[(16 + ul) * 33 + b] + preS[64 * 33 + (16 + ul) * 33 + b] + addp[it][1];
        float o  = preS[(32 + ul) * 33 + b] + preS[64 * 33 + (32 + ul) * 33 + b] + addp[it][2];
        float gg = preS[(48 + ul) * 33 + b] + preS[64 * 33 + (48 + ul) * 33 + b] + addp[it][3];
        const float m  = mpre[it];
        const float cp = cpre[it];
        const float hp = hpre[it];

        float cn = sigf(f) * cp + sigf(i) * tanhfast(gg);
        cn = cn * m + cp * (1.f - m);
        float hn = sigf(o) * tanhfast(cn);
        hn = hn * m + hp * (1.f - m);

        g_c[L][b][j] = cn;
        g_h[L][b][j] = hn;
        g_hf[p ^ 1][L][b][j] = __float2half(hn);
        if (L) out[((size_t)b * TT + t) * HH + j] = hn;
    }
}

// ---------------------------------------------------------------------------
extern "C" void kernel_launch(void* const* d_in, const int* in_sizes, int n_in,
                              void* d_out, int out_size)
{
    const float* x     = (const float*)d_in[0];
    const float* mask  = (const float*)d_in[1];
    const float* W_ih0 = (const float*)d_in[2];
    const float* W_hh0 = (const float*)d_in[3];
    const float* bs0   = (const float*)d_in[4];
    const float* W_ih1 = (const float*)d_in[5];
    const float* W_hh1 = (const float*)d_in[6];
    const float* bs1   = (const float*)d_in[7];
    float* out = (float*)d_out;

    static bool attr_done = false;
    if (!attr_done) {
        cudaFuncSetAttribute(x0_gemm, cudaFuncAttributeMaxDynamicSharedMemorySize, X0SM);
        cudaFuncSetAttribute(lstm_step, cudaFuncAttributeMaxDynamicSharedMemorySize, SMEM_STEP);
        attr_done = true;
    }

    prep_weights<<<dim3(KK / 32, C4 / 32, 2), dim3(32, 8)>>>(W_ih0, W_hh0, W_ih1, W_hh1);
    prep_x<<<2048, 256>>>(x);
    zero_states<<<512, 256>>>();
    x0_gemm<<<dim3(16, 128), 256, X0SM>>>(bs0);

    // PDL chain over the 256 dependent step kernels
    cudaLaunchAttribute attrs[1];
    attrs[0].id = cudaLaunchAttributeProgrammaticStreamSerialization;
    attrs[0].val.programmaticStreamSerializationAllowed = 1;

    cudaLaunchConfig_t cfg = {};
    cfg.gridDim  = dim3(128, 1, 1);
    cfg.blockDim = dim3(256, 1, 1);
    cfg.dynamicSmemBytes = SMEM_STEP;
    cfg.stream = 0;
    cfg.attrs = attrs;
    cfg.numAttrs = 1;

    for (int t = 0; t < TT; t++) {
        cudaLaunchKernelEx(&cfg, lstm_step, t, mask, bs1, out);
    }

    if (out_size >= BZ * TT * HH + BZ * TT) {
        copy_mask<<<(BZ * TT + 255) / 256, 256>>>(mask, out + (size_t)BZ * TT * HH);
    }
}